// round 1
// baseline (speedup 1.0000x reference)
#include <cuda_runtime.h>

#define NN   100000
#define FEAT 256
#define HID  128
#define OUTD 64
#define NE   3200000

// ---------------- scratch (static device memory; no allocations) ----------------
__device__ float g_xs[(size_t)NN * HID];
__device__ float g_xt[(size_t)NN * HID];
__device__ float g_fs[(size_t)NN * HID];
__device__ float g_ft[(size_t)NN * HID];
__device__ float g_cs[(size_t)NN * HID];
__device__ float g_ct[(size_t)NN * HID];
__device__ int   g_rp [NN + 1];
__device__ int   g_rpT[NN + 1];
__device__ int   g_off [NN];
__device__ int   g_offT[NN];
__device__ int   g_ci [NE];
__device__ int   g_ciT[NE];
__device__ float g_wv [NE];
__device__ float g_wvT[NE];

// ---------------- CSR build ----------------
__global__ void zero_deg_kernel() {
    int i = blockIdx.x * blockDim.x + threadIdx.x;
    if (i < NN) { g_off[i] = 0; g_offT[i] = 0; }
}

__global__ void hist_kernel(const int* __restrict__ row, const int* __restrict__ col, int E) {
    int e = blockIdx.x * blockDim.x + threadIdx.x;
    if (e < E) {
        atomicAdd(&g_off [row[e]], 1);
        atomicAdd(&g_offT[col[e]], 1);
    }
}

// one block, 1024 threads: exclusive scan of both degree arrays -> row_ptr + scatter cursors
__global__ void scan2_kernel(int E) {
    __shared__ int sh[1024];
    int t = threadIdx.x;
    const int C = (NN + 1023) / 1024;
    for (int a = 0; a < 2; a++) {
        int* deg = a ? g_offT : g_off;
        int* rp  = a ? g_rpT  : g_rp;
        int lo = t * C;
        int hi = lo + C; if (hi > NN) hi = NN;
        int s = 0;
        for (int i = lo; i < hi; i++) s += deg[i];
        __syncthreads();
        sh[t] = s;
        __syncthreads();
        for (int off = 1; off < 1024; off <<= 1) {
            int x = (t >= off) ? sh[t - off] : 0;
            __syncthreads();
            sh[t] += x;
            __syncthreads();
        }
        int run = sh[t] - s;  // exclusive prefix
        for (int i = lo; i < hi; i++) {
            int d = deg[i];
            rp[i]  = run;
            deg[i] = run;   // scatter cursor
            run += d;
        }
        if (t == 0) rp[NN] = E;
    }
}

__global__ void scatter_kernel(const int* __restrict__ row, const int* __restrict__ col,
                               const float* __restrict__ w, int E) {
    int e = blockIdx.x * blockDim.x + threadIdx.x;
    if (e < E) {
        int r = row[e], c = col[e];
        float wt = w[e];
        int p = atomicAdd(&g_off[r], 1);
        g_ci[p] = c; g_wv[p] = wt;
        int q = atomicAdd(&g_offT[c], 1);
        g_ciT[q] = r; g_wvT[q] = wt;
    }
}

// ---------------- input GEMMs: x = A @ W + b ; feat = w0 * x ----------------
// BM=64, BN=128(=HID), BK=16, 256 threads, each thread 8x4 outputs.
__global__ __launch_bounds__(256) void gemm_in_kernel(
    const float* __restrict__ A0, const float* __restrict__ A1,
    const float* __restrict__ W0, const float* __restrict__ b0,
    const float* __restrict__ W1, const float* __restrict__ b1,
    const float* __restrict__ ws, const float* __restrict__ wt)
{
    const float* A; const float* W; const float* b;
    float* X; float* F; float w0;
    if (blockIdx.y == 0) { A = A0; W = W0; b = b0; X = g_xs; F = g_fs; w0 = ws[0]; }
    else                 { A = A1; W = W1; b = b1; X = g_xt; F = g_ft; w0 = wt[0]; }

    __shared__ float As[16][64];
    __shared__ float Ws[16][128];
    int tid = threadIdx.x;
    int tx = tid & 31;          // 32 col-groups of 4
    int ty = tid >> 5;          // 8 row-groups of 8
    int row0 = blockIdx.x * 64;

    float c[8][4];
#pragma unroll
    for (int i = 0; i < 8; i++)
#pragma unroll
        for (int j = 0; j < 4; j++) c[i][j] = 0.f;

    int ar = tid >> 2;          // 0..63
    int ak = (tid & 3) * 4;     // 0,4,8,12

    for (int kt = 0; kt < FEAT; kt += 16) {
        float4 av = make_float4(0.f, 0.f, 0.f, 0.f);
        int grow = row0 + ar;
        if (grow < NN) av = *(const float4*)(A + (size_t)grow * FEAT + kt + ak);
        As[ak + 0][ar] = av.x; As[ak + 1][ar] = av.y;
        As[ak + 2][ar] = av.z; As[ak + 3][ar] = av.w;
#pragma unroll
        for (int i = 0; i < 2; i++) {
            int q = tid + i * 256;      // 0..511 float4s
            int k = q >> 5, n4 = q & 31;
            *(float4*)&Ws[k][n4 * 4] = *(const float4*)(W + (size_t)(kt + k) * HID + n4 * 4);
        }
        __syncthreads();
#pragma unroll
        for (int kk = 0; kk < 16; kk++) {
            float a[8];
#pragma unroll
            for (int i = 0; i < 8; i++) a[i] = As[kk][ty * 8 + i];
            float4 w4 = *(float4*)&Ws[kk][tx * 4];
            float wr[4] = { w4.x, w4.y, w4.z, w4.w };
#pragma unroll
            for (int i = 0; i < 8; i++)
#pragma unroll
                for (int j = 0; j < 4; j++) c[i][j] += a[i] * wr[j];
        }
        __syncthreads();
    }

    float bb[4];
#pragma unroll
    for (int j = 0; j < 4; j++) bb[j] = b[tx * 4 + j];
#pragma unroll
    for (int i = 0; i < 8; i++) {
        int row = row0 + ty * 8 + i;
        if (row < NN) {
            float4 xv, fv;
            xv.x = c[i][0] + bb[0]; xv.y = c[i][1] + bb[1];
            xv.z = c[i][2] + bb[2]; xv.w = c[i][3] + bb[3];
            fv.x = w0 * xv.x; fv.y = w0 * xv.y; fv.z = w0 * xv.z; fv.w = w0 * xv.w;
            *(float4*)(X + (size_t)row * HID + tx * 4) = xv;
            *(float4*)(F + (size_t)row * HID + tx * 4) = fv;
        }
    }
}

// ---------------- CSR gather SPMM: one warp per row, lane = 4 feats ----------------
// which: 0 = source path (adj), 1 = target path (adj^T). pp: ping-pong selector.
__global__ __launch_bounds__(256) void spmm_kernel(int which, int pp,
                                                   const float* __restrict__ whp)
{
    int w = (blockIdx.x * blockDim.x + threadIdx.x) >> 5;
    int lane = threadIdx.x & 31;
    if (w >= NN) return;

    const int*   rp;  const int* ci;  const float* wv;
    const float* xin; float* xout; float* feat;
    if (which == 0) {
        rp = g_rp;  ci = g_ci;  wv = g_wv;  feat = g_fs;
        xin  = pp ? g_cs : g_xs;
        xout = pp ? g_xs : g_cs;
    } else {
        rp = g_rpT; ci = g_ciT; wv = g_wvT; feat = g_ft;
        xin  = pp ? g_ct : g_xt;
        xout = pp ? g_xt : g_ct;
    }

    int s = rp[w], e = rp[w + 1];
    float ax = 0.f, ay = 0.f, az = 0.f, aw = 0.f;
    for (int i = s; i < e; i++) {
        int   c = __ldg(&ci[i]);
        float t = __ldg(&wv[i]);
        float4 v = *(const float4*)(xin + (size_t)c * HID + lane * 4);
        ax += t * v.x; ay += t * v.y; az += t * v.z; aw += t * v.w;
    }
    float wh = *whp;
    size_t o = (size_t)w * HID + lane * 4;
    float4 r; r.x = ax; r.y = ay; r.z = az; r.w = aw;
    *(float4*)(xout + o) = r;
    float4 f = *(float4*)(feat + o);
    f.x += wh * ax; f.y += wh * ay; f.z += wh * az; f.w += wh * aw;
    *(float4*)(feat + o) = f;
}

// ---------------- output GEMM: out = [fs | ft] @ W_node + b_node ----------------
// BM=64, BN=64(=OUT), BK=16, 256 threads, each thread 4x4 outputs.
__global__ __launch_bounds__(256) void gemm_out_kernel(
    const float* __restrict__ Wn, const float* __restrict__ bn, float* __restrict__ out)
{
    __shared__ float As[16][64];
    __shared__ float Ws[16][64];
    int tid = threadIdx.x;
    int tx = tid & 15;          // 16 col-groups of 4
    int ty = tid >> 4;          // 16 row-groups of 4
    int row0 = blockIdx.x * 64;

    float c[4][4];
#pragma unroll
    for (int i = 0; i < 4; i++)
#pragma unroll
        for (int j = 0; j < 4; j++) c[i][j] = 0.f;

    int ar = tid >> 2;          // 0..63
    int ak = (tid & 3) * 4;     // 0,4,8,12
    int wk = tid >> 4, wn4 = tid & 15;

    for (int kt = 0; kt < 2 * HID; kt += 16) {
        const float* Abase = (kt < HID) ? g_fs : g_ft;
        int kloc = (kt < HID) ? kt : kt - HID;
        float4 av = make_float4(0.f, 0.f, 0.f, 0.f);
        int grow = row0 + ar;
        if (grow < NN) av = *(const float4*)(Abase + (size_t)grow * HID + kloc + ak);
        As[ak + 0][ar] = av.x; As[ak + 1][ar] = av.y;
        As[ak + 2][ar] = av.z; As[ak + 3][ar] = av.w;
        *(float4*)&Ws[wk][wn4 * 4] = *(const float4*)(Wn + (size_t)(kt + wk) * OUTD + wn4 * 4);
        __syncthreads();
#pragma unroll
        for (int kk = 0; kk < 16; kk++) {
            float a[4];
#pragma unroll
            for (int i = 0; i < 4; i++) a[i] = As[kk][ty * 4 + i];
            float4 w4 = *(float4*)&Ws[kk][tx * 4];
            float wr[4] = { w4.x, w4.y, w4.z, w4.w };
#pragma unroll
            for (int i = 0; i < 4; i++)
#pragma unroll
                for (int j = 0; j < 4; j++) c[i][j] += a[i] * wr[j];
        }
        __syncthreads();
    }

    float bb[4];
#pragma unroll
    for (int j = 0; j < 4; j++) bb[j] = bn[tx * 4 + j];
#pragma unroll
    for (int i = 0; i < 4; i++) {
        int row = row0 + ty * 4 + i;
        if (row < NN) {
            float4 ov;
            ov.x = c[i][0] + bb[0]; ov.y = c[i][1] + bb[1];
            ov.z = c[i][2] + bb[2]; ov.w = c[i][3] + bb[3];
            *(float4*)(out + (size_t)row * OUTD + tx * 4) = ov;
        }
    }
}

// ---------------- launch ----------------
extern "C" void kernel_launch(void* const* d_in, const int* in_sizes, int n_in,
                              void* d_out, int out_size)
{
    const float* fsrc  = (const float*)d_in[0];
    const float* ftgt  = (const float*)d_in[1];
    const int*   erow  = (const int*)d_in[2];
    const int*   ecol  = (const int*)d_in[3];
    const float* ew    = (const float*)d_in[4];
    const float* Wsrc  = (const float*)d_in[5];
    const float* bsrc  = (const float*)d_in[6];
    const float* Wtgt  = (const float*)d_in[7];
    const float* btgt  = (const float*)d_in[8];
    const float* ws    = (const float*)d_in[9];
    const float* wt    = (const float*)d_in[10];
    const float* Wnode = (const float*)d_in[11];
    const float* bnode = (const float*)d_in[12];
    float* out = (float*)d_out;
    int E = in_sizes[2];
    if (E > NE) E = NE;

    // CSR build (overlappable with gemm_in; all on default stream for capture safety)
    zero_deg_kernel<<<(NN + 255) / 256, 256>>>();

    dim3 gg((NN + 63) / 64, 2);
    gemm_in_kernel<<<gg, 256>>>(fsrc, ftgt, Wsrc, bsrc, Wtgt, btgt, ws, wt);

    int eg = (E + 255) / 256;
    hist_kernel<<<eg, 256>>>(erow, ecol, E);
    scan2_kernel<<<1, 1024>>>(E);
    scatter_kernel<<<eg, 256>>>(erow, ecol, ew, E);

    int sg = (NN * 32 + 255) / 256;  // one warp per row
    // hop 1: xs -> cs, xt -> ct
    spmm_kernel<<<sg, 256>>>(0, 0, ws + 1);
    spmm_kernel<<<sg, 256>>>(1, 0, wt + 1);
    // hop 2: cs -> xs, ct -> xt
    spmm_kernel<<<sg, 256>>>(0, 1, ws + 2);
    spmm_kernel<<<sg, 256>>>(1, 1, wt + 2);
    // hop 3: xs -> cs, xt -> ct
    spmm_kernel<<<sg, 256>>>(0, 0, ws + 3);
    spmm_kernel<<<sg, 256>>>(1, 0, wt + 3);

    gemm_out_kernel<<<(NN + 63) / 64, 256>>>(Wnode, bnode, out);
}

// round 7
// speedup vs baseline: 1.0733x; 1.0733x over previous
#include <cuda_runtime.h>
#include <cuda_fp16.h>

#define NN   100000
#define FEAT 256
#define HID  128
#define OUTD 64
#define NE   3200000
#define SCB  1024
#define NBLK ((NN + SCB - 1) / SCB)   // 98

// ---------------- scratch (static device memory; no allocations) ----------------
__device__ __half g_xs[(size_t)NN * HID];
__device__ __half g_xt[(size_t)NN * HID];
__device__ __half g_cs[(size_t)NN * HID];
__device__ __half g_ct[(size_t)NN * HID];
__device__ float  g_fs[(size_t)NN * HID];
__device__ float  g_ft[(size_t)NN * HID];
__device__ int    g_rp [NN + 1];
__device__ int    g_rpT[NN + 1];
__device__ int    g_off [NN];
__device__ int    g_offT[NN];
__device__ int    g_part[2][128];
__device__ int2   g_ep [NE];    // packed (col, weight-bits)
__device__ int2   g_epT[NE];

// ---------------- CSR build ----------------
__global__ void zero_deg_kernel() {
    int i = blockIdx.x * blockDim.x + threadIdx.x;
    if (i < NN) { g_off[i] = 0; g_offT[i] = 0; }
}

__global__ void hist_kernel(const int* __restrict__ row, const int* __restrict__ col, int E) {
    int e = blockIdx.x * blockDim.x + threadIdx.x;
    if (e < E) {
        atomicAdd(&g_off [row[e]], 1);
        atomicAdd(&g_offT[col[e]], 1);
    }
}

// phase 1: per-block sums of both degree arrays
__global__ __launch_bounds__(SCB) void scan_partial_kernel() {
    int arr = blockIdx.y;
    const int* deg = arr ? g_offT : g_off;
    int i = blockIdx.x * SCB + threadIdx.x;
    int v = (i < NN) ? deg[i] : 0;
    __shared__ int sh[SCB];
    sh[threadIdx.x] = v;
    __syncthreads();
    for (int off = SCB / 2; off > 0; off >>= 1) {
        if (threadIdx.x < off) sh[threadIdx.x] += sh[threadIdx.x + off];
        __syncthreads();
    }
    if (threadIdx.x == 0) g_part[arr][blockIdx.x] = sh[0];
}

// phase 2: exclusive scan of the 98 partials per array (one warp per array)
__global__ void scan_part2_kernel() {
    int warp = threadIdx.x >> 5, lane = threadIdx.x & 31;
    if (warp < 2) {
        int* p = g_part[warp];
        int carry = 0;
        for (int base = 0; base < NBLK; base += 32) {
            int i = base + lane;
            int v = (i < NBLK) ? p[i] : 0;
            int inc = v;
#pragma unroll
            for (int off = 1; off < 32; off <<= 1) {
                int x = __shfl_up_sync(0xffffffffu, inc, off);
                if (lane >= off) inc += x;
            }
            if (i < NBLK) p[i] = inc - v + carry;
            carry += __shfl_sync(0xffffffffu, inc, 31);
        }
    }
}

// phase 3: per-block exclusive scan + offset -> row_ptr and scatter cursors
__global__ __launch_bounds__(SCB) void scan_final_kernel(int E) {
    int arr = blockIdx.y;
    int* deg = arr ? g_offT : g_off;
    int* rp  = arr ? g_rpT  : g_rp;
    int i = blockIdx.x * SCB + threadIdx.x;
    int v = (i < NN) ? deg[i] : 0;
    __shared__ int sh[SCB];
    sh[threadIdx.x] = v;
    __syncthreads();
    for (int off = 1; off < SCB; off <<= 1) {
        int x = (threadIdx.x >= off) ? sh[threadIdx.x - off] : 0;
        __syncthreads();
        sh[threadIdx.x] += x;
        __syncthreads();
    }
    int excl = sh[threadIdx.x] - v + g_part[arr][blockIdx.x];
    if (i < NN) { rp[i] = excl; deg[i] = excl; }
    if (blockIdx.x == 0 && threadIdx.x == 0) rp[NN] = E;
}

__global__ void scatter_kernel(const int* __restrict__ row, const int* __restrict__ col,
                               const float* __restrict__ w, int E) {
    int e = blockIdx.x * blockDim.x + threadIdx.x;
    if (e < E) {
        int r = row[e], c = col[e];
        float wt = w[e];
        int wb = __float_as_int(wt);
        int p = atomicAdd(&g_off[r], 1);
        g_ep[p] = make_int2(c, wb);
        int q = atomicAdd(&g_offT[c], 1);
        g_epT[q] = make_int2(r, wb);
    }
}

// ---------------- input GEMMs: x = A @ W + b (half store) ; feat = w0 * x (fp32) ----------------
__global__ __launch_bounds__(256) void gemm_in_kernel(
    const float* __restrict__ A0, const float* __restrict__ A1,
    const float* __restrict__ W0, const float* __restrict__ b0,
    const float* __restrict__ W1, const float* __restrict__ b1,
    const float* __restrict__ ws, const float* __restrict__ wt)
{
    const float* A; const float* W; const float* b;
    __half* X; float* F; float w0;
    if (blockIdx.y == 0) { A = A0; W = W0; b = b0; X = g_xs; F = g_fs; w0 = ws[0]; }
    else                 { A = A1; W = W1; b = b1; X = g_xt; F = g_ft; w0 = wt[0]; }

    __shared__ float As[16][64];
    __shared__ float Ws[16][128];
    int tid = threadIdx.x;
    int tx = tid & 31;
    int ty = tid >> 5;
    int row0 = blockIdx.x * 64;

    float c[8][4];
#pragma unroll
    for (int i = 0; i < 8; i++)
#pragma unroll
        for (int j = 0; j < 4; j++) c[i][j] = 0.f;

    int ar = tid >> 2;
    int ak = (tid & 3) * 4;

    for (int kt = 0; kt < FEAT; kt += 16) {
        float4 av = make_float4(0.f, 0.f, 0.f, 0.f);
        int grow = row0 + ar;
        if (grow < NN) av = *(const float4*)(A + (size_t)grow * FEAT + kt + ak);
        As[ak + 0][ar] = av.x; As[ak + 1][ar] = av.y;
        As[ak + 2][ar] = av.z; As[ak + 3][ar] = av.w;
#pragma unroll
        for (int i = 0; i < 2; i++) {
            int q = tid + i * 256;
            int k = q >> 5, n4 = q & 31;
            *(float4*)&Ws[k][n4 * 4] = *(const float4*)(W + (size_t)(kt + k) * HID + n4 * 4);
        }
        __syncthreads();
#pragma unroll
        for (int kk = 0; kk < 16; kk++) {
            float a[8];
#pragma unroll
            for (int i = 0; i < 8; i++) a[i] = As[kk][ty * 8 + i];
            float4 w4 = *(float4*)&Ws[kk][tx * 4];
            float wr[4] = { w4.x, w4.y, w4.z, w4.w };
#pragma unroll
            for (int i = 0; i < 8; i++)
#pragma unroll
                for (int j = 0; j < 4; j++) c[i][j] += a[i] * wr[j];
        }
        __syncthreads();
    }

    float bb[4];
#pragma unroll
    for (int j = 0; j < 4; j++) bb[j] = b[tx * 4 + j];
#pragma unroll
    for (int i = 0; i < 8; i++) {
        int row = row0 + ty * 8 + i;
        if (row < NN) {
            float4 xv, fv;
            xv.x = c[i][0] + bb[0]; xv.y = c[i][1] + bb[1];
            xv.z = c[i][2] + bb[2]; xv.w = c[i][3] + bb[3];
            fv.x = w0 * xv.x; fv.y = w0 * xv.y; fv.z = w0 * xv.z; fv.w = w0 * xv.w;
            __half2 h0 = __floats2half2_rn(xv.x, xv.y);
            __half2 h1 = __floats2half2_rn(xv.z, xv.w);
            uint2 u; u.x = *(unsigned*)&h0; u.y = *(unsigned*)&h1;
            *(uint2*)(X + (size_t)row * HID + tx * 4) = u;
            *(float4*)(F + (size_t)row * HID + tx * 4) = fv;
        }
    }
}

// ---------------- CSR gather SPMM (half in / half out, fp32 accumulate + feat) ----------------
// blockIdx.y: 0 = source path (adj), 1 = target path (adj^T). pp: ping-pong selector.
__global__ __launch_bounds__(256) void spmm_kernel(int pp, int hop,
                                                   const float* __restrict__ wsp,
                                                   const float* __restrict__ wtp)
{
    int which = blockIdx.y;
    int w = (blockIdx.x * blockDim.x + threadIdx.x) >> 5;
    int lane = threadIdx.x & 31;
    if (w >= NN) return;

    const int* rp; const int2* ep;
    const __half* xin; __half* xout; float* feat; float wh;
    if (which == 0) {
        rp = g_rp;  ep = g_ep;  feat = g_fs; wh = wsp[hop];
        xin  = pp ? g_cs : g_xs;
        xout = pp ? g_xs : g_cs;
    } else {
        rp = g_rpT; ep = g_epT; feat = g_ft; wh = wtp[hop];
        xin  = pp ? g_ct : g_xt;
        xout = pp ? g_xt : g_ct;
    }

    int s = rp[w], e = rp[w + 1];
    float ax = 0.f, ay = 0.f, az = 0.f, aw = 0.f;
    for (int i = s; i < e; i++) {
        int2 pr = __ldg(&ep[i]);
        int   c = pr.x;
        float t = __int_as_float(pr.y);
        uint2 u = __ldg((const uint2*)(xin + (size_t)c * HID + lane * 4));
        __half2 h0 = *(__half2*)&u.x;
        __half2 h1 = *(__half2*)&u.y;
        float2 f0 = __half22float2(h0);
        float2 f1 = __half22float2(h1);
        ax += t * f0.x; ay += t * f0.y; az += t * f1.x; aw += t * f1.y;
    }
    size_t o = (size_t)w * HID + lane * 4;
    __half2 o0 = __floats2half2_rn(ax, ay);
    __half2 o1 = __floats2half2_rn(az, aw);
    uint2 uo; uo.x = *(unsigned*)&o0; uo.y = *(unsigned*)&o1;
    *(uint2*)(xout + o) = uo;
    float4 f = *(float4*)(feat + o);
    f.x += wh * ax; f.y += wh * ay; f.z += wh * az; f.w += wh * aw;
    *(float4*)(feat + o) = f;
}

// ---------------- output GEMM: out = [fs | ft] @ W_node + b_node ----------------
__global__ __launch_bounds__(256) void gemm_out_kernel(
    const float* __restrict__ Wn, const float* __restrict__ bn, float* __restrict__ out)
{
    __shared__ float As[16][64];
    __shared__ float Ws[16][64];
    int tid = threadIdx.x;
    int tx = tid & 15;
    int ty = tid >> 4;
    int row0 = blockIdx.x * 64;

    float c[4][4];
#pragma unroll
    for (int i = 0; i < 4; i++)
#pragma unroll
        for (int j = 0; j < 4; j++) c[i][j] = 0.f;

    int ar = tid >> 2;
    int ak = (tid & 3) * 4;
    int wk = tid >> 4, wn4 = tid & 15;

    for (int kt = 0; kt < 2 * HID; kt += 16) {
        const float* Abase = (kt < HID) ? g_fs : g_ft;
        int kloc = (kt < HID) ? kt : kt - HID;
        float4 av = make_float4(0.f, 0.f, 0.f, 0.f);
        int grow = row0 + ar;
        if (grow < NN) av = *(const float4*)(Abase + (size_t)grow * HID + kloc + ak);
        As[ak + 0][ar] = av.x; As[ak + 1][ar] = av.y;
        As[ak + 2][ar] = av.z; As[ak + 3][ar] = av.w;
        *(float4*)&Ws[wk][wn4 * 4] = *(const float4*)(Wn + (size_t)(kt + wk) * OUTD + wn4 * 4);
        __syncthreads();
#pragma unroll
        for (int kk = 0; kk < 16; kk++) {
            float a[4];
#pragma unroll
            for (int i = 0; i < 4; i++) a[i] = As[kk][ty * 4 + i];
            float4 w4 = *(float4*)&Ws[kk][tx * 4];
            float wr[4] = { w4.x, w4.y, w4.z, w4.w };
#pragma unroll
            for (int i = 0; i < 4; i++)
#pragma unroll
                for (int j = 0; j < 4; j++) c[i][j] += a[i] * wr[j];
        }
        __syncthreads();
    }

    float bb[4];
#pragma unroll
    for (int j = 0; j < 4; j++) bb[j] = bn[tx * 4 + j];
#pragma unroll
    for (int i = 0; i < 4; i++) {
        int row = row0 + ty * 4 + i;
        if (row < NN) {
            float4 ov;
            ov.x = c[i][0] + bb[0]; ov.y = c[i][1] + bb[1];
            ov.z = c[i][2] + bb[2]; ov.w = c[i][3] + bb[3];
            *(float4*)(out + (size_t)row * OUTD + tx * 4) = ov;
        }
    }
}

// ---------------- launch ----------------
extern "C" void kernel_launch(void* const* d_in, const int* in_sizes, int n_in,
                              void* d_out, int out_size)
{
    const float* fsrc  = (const float*)d_in[0];
    const float* ftgt  = (const float*)d_in[1];
    const int*   erow  = (const int*)d_in[2];
    const int*   ecol  = (const int*)d_in[3];
    const float* ew    = (const float*)d_in[4];
    const float* Wsrc  = (const float*)d_in[5];
    const float* bsrc  = (const float*)d_in[6];
    const float* Wtgt  = (const float*)d_in[7];
    const float* btgt  = (const float*)d_in[8];
    const float* ws    = (const float*)d_in[9];
    const float* wt    = (const float*)d_in[10];
    const float* Wnode = (const float*)d_in[11];
    const float* bnode = (const float*)d_in[12];
    float* out = (float*)d_out;
    int E = in_sizes[2];
    if (E > NE) E = NE;

    zero_deg_kernel<<<(NN + 255) / 256, 256>>>();

    dim3 gg((NN + 63) / 64, 2);
    gemm_in_kernel<<<gg, 256>>>(fsrc, ftgt, Wsrc, bsrc, Wtgt, btgt, ws, wt);

    int eg = (E + 255) / 256;
    hist_kernel<<<eg, 256>>>(erow, ecol, E);
    dim3 sgr(NBLK, 2);
    scan_partial_kernel<<<sgr, SCB>>>();
    scan_part2_kernel<<<1, 64>>>();
    scan_final_kernel<<<sgr, SCB>>>(E);
    scatter_kernel<<<eg, 256>>>(erow, ecol, ew, E);

    dim3 sg((NN * 32 + 255) / 256, 2);  // one warp per row, y = path
    spmm_kernel<<<sg, 256>>>(0, 1, ws, wt);  // hop 1: x -> c
    spmm_kernel<<<sg, 256>>>(1, 2, ws, wt);  // hop 2: c -> x
    spmm_kernel<<<sg, 256>>>(0, 3, ws, wt);  // hop 3: x -> c

    gemm_out_kernel<<<(NN + 63) / 64, 256>>>(Wnode, bnode, out);
}

// round 10
// speedup vs baseline: 1.7947x; 1.6721x over previous
#include <cuda_runtime.h>
#include <cuda_fp16.h>
#include <mma.h>

using namespace nvcuda;

#define NN   100000
#define FEAT 256
#define HID  128
#define OUTD 64
#define NE   3200000
#define SCB  1024
#define NBLK ((NN + SCB - 1) / SCB)   // 98

// ---------------- scratch (static device memory; no allocations) ----------------
__device__ __half g_xs[(size_t)NN * HID];
__device__ __half g_xt[(size_t)NN * HID];
__device__ __half g_cs[(size_t)NN * HID];
__device__ __half g_ct[(size_t)NN * HID];
__device__ float  g_fs[(size_t)NN * HID];
__device__ float  g_ft[(size_t)NN * HID];
__device__ int    g_rp [NN + 1];
__device__ int    g_rpT[NN + 1];
__device__ int    g_off [NN];
__device__ int    g_offT[NN];
__device__ int    g_part[2][128];
__device__ int2   g_ep [NE];    // packed (col, weight-bits)
__device__ int2   g_epT[NE];

// ---------------- CSR build ----------------
__global__ void zero_deg_kernel() {
    int i = blockIdx.x * blockDim.x + threadIdx.x;
    if (i < NN) { g_off[i] = 0; g_offT[i] = 0; }
}

__global__ void hist_kernel(const int* __restrict__ row, const int* __restrict__ col, int E) {
    int e = blockIdx.x * blockDim.x + threadIdx.x;
    if (e < E) {
        atomicAdd(&g_off [row[e]], 1);
        atomicAdd(&g_offT[col[e]], 1);
    }
}

__global__ __launch_bounds__(SCB) void scan_partial_kernel() {
    int arr = blockIdx.y;
    const int* deg = arr ? g_offT : g_off;
    int i = blockIdx.x * SCB + threadIdx.x;
    int v = (i < NN) ? deg[i] : 0;
    __shared__ int sh[SCB];
    sh[threadIdx.x] = v;
    __syncthreads();
    for (int off = SCB / 2; off > 0; off >>= 1) {
        if (threadIdx.x < off) sh[threadIdx.x] += sh[threadIdx.x + off];
        __syncthreads();
    }
    if (threadIdx.x == 0) g_part[arr][blockIdx.x] = sh[0];
}

__global__ void scan_part2_kernel() {
    int warp = threadIdx.x >> 5, lane = threadIdx.x & 31;
    if (warp < 2) {
        int* p = g_part[warp];
        int carry = 0;
        for (int base = 0; base < NBLK; base += 32) {
            int i = base + lane;
            int v = (i < NBLK) ? p[i] : 0;
            int inc = v;
#pragma unroll
            for (int off = 1; off < 32; off <<= 1) {
                int x = __shfl_up_sync(0xffffffffu, inc, off);
                if (lane >= off) inc += x;
            }
            if (i < NBLK) p[i] = inc - v + carry;
            carry += __shfl_sync(0xffffffffu, inc, 31);
        }
    }
}

__global__ __launch_bounds__(SCB) void scan_final_kernel(int E) {
    int arr = blockIdx.y;
    int* deg = arr ? g_offT : g_off;
    int* rp  = arr ? g_rpT  : g_rp;
    int i = blockIdx.x * SCB + threadIdx.x;
    int v = (i < NN) ? deg[i] : 0;
    __shared__ int sh[SCB];
    sh[threadIdx.x] = v;
    __syncthreads();
    for (int off = 1; off < SCB; off <<= 1) {
        int x = (threadIdx.x >= off) ? sh[threadIdx.x - off] : 0;
        __syncthreads();
        sh[threadIdx.x] += x;
        __syncthreads();
    }
    int excl = sh[threadIdx.x] - v + g_part[arr][blockIdx.x];
    if (i < NN) { rp[i] = excl; deg[i] = excl; }
    if (blockIdx.x == 0 && threadIdx.x == 0) rp[NN] = E;
}

__global__ void scatter_kernel(const int* __restrict__ row, const int* __restrict__ col,
                               const float* __restrict__ w, int E) {
    int e = blockIdx.x * blockDim.x + threadIdx.x;
    if (e < E) {
        int r = row[e], c = col[e];
        int wb = __float_as_int(w[e]);
        int p = atomicAdd(&g_off[r], 1);
        g_ep[p] = make_int2(c, wb);
        int q = atomicAdd(&g_offT[c], 1);
        g_epT[q] = make_int2(r, wb);
    }
}

// ---------------- helpers: fp32 -> (hi, lo) fp16 split ----------------
__device__ __forceinline__ void split_half(float v, __half& hi, __half& lo) {
    hi = __float2half_rn(v);
    lo = __float2half_rn(v - __half2float(hi));
}

// ---------------- input GEMMs (tensor, split-3 fp16): x = A @ W + b ----------------
// BM=64, BN=128, BK=32; 256 threads = 8 warps (2x4), each warp 32x32 (2x2 wmma frags)
struct GInShared {
    union {
        struct {
            __half Ahi[64][40];
            __half Alo[64][40];
            __half Whi[32][136];
            __half Wlo[32][136];
        } ld;
        float Csm[64][132];
    } u;
};

__global__ __launch_bounds__(256) void gemm_in_tc_kernel(
    const float* __restrict__ A0, const float* __restrict__ A1,
    const float* __restrict__ W0, const float* __restrict__ b0,
    const float* __restrict__ W1, const float* __restrict__ b1,
    const float* __restrict__ ws, const float* __restrict__ wt)
{
    const float* A; const float* W; const float* b;
    __half* X; float* F; float w0;
    if (blockIdx.y == 0) { A = A0; W = W0; b = b0; X = g_xs; F = g_fs; w0 = ws[0]; }
    else                 { A = A1; W = W1; b = b1; X = g_xt; F = g_ft; w0 = wt[0]; }

    __shared__ GInShared sh;
    int tid = threadIdx.x;
    int warp = tid >> 5;
    int wm = warp >> 2;          // 0..1
    int wn = warp & 3;           // 0..3
    int row0 = blockIdx.x * 64;

    wmma::fragment<wmma::accumulator, 16, 16, 16, float> c[2][2];
#pragma unroll
    for (int i = 0; i < 2; i++)
#pragma unroll
        for (int j = 0; j < 2; j++) wmma::fill_fragment(c[i][j], 0.f);

    for (int kt = 0; kt < FEAT; kt += 32) {
        // load A tile 64x32 (512 float4, 2 per thread), split to hi/lo
#pragma unroll
        for (int t = 0; t < 2; t++) {
            int idx = tid + t * 256;
            int r = idx >> 3;            // 0..63
            int kq = (idx & 7) * 4;      // 0,4,..,28
            float4 av = make_float4(0.f, 0.f, 0.f, 0.f);
            int grow = row0 + r;
            if (grow < NN) av = *(const float4*)(A + (size_t)grow * FEAT + kt + kq);
            __half hi, lo;
            split_half(av.x, hi, lo); sh.u.ld.Ahi[r][kq + 0] = hi; sh.u.ld.Alo[r][kq + 0] = lo;
            split_half(av.y, hi, lo); sh.u.ld.Ahi[r][kq + 1] = hi; sh.u.ld.Alo[r][kq + 1] = lo;
            split_half(av.z, hi, lo); sh.u.ld.Ahi[r][kq + 2] = hi; sh.u.ld.Alo[r][kq + 2] = lo;
            split_half(av.w, hi, lo); sh.u.ld.Ahi[r][kq + 3] = hi; sh.u.ld.Alo[r][kq + 3] = lo;
        }
        // load W tile 32x128 (1024 float4, 4 per thread)
#pragma unroll
        for (int t = 0; t < 4; t++) {
            int idx = tid + t * 256;
            int r = idx >> 5;            // 0..31
            int nq = (idx & 31) * 4;     // 0..124
            float4 wv = *(const float4*)(W + (size_t)(kt + r) * HID + nq);
            __half hi, lo;
            split_half(wv.x, hi, lo); sh.u.ld.Whi[r][nq + 0] = hi; sh.u.ld.Wlo[r][nq + 0] = lo;
            split_half(wv.y, hi, lo); sh.u.ld.Whi[r][nq + 1] = hi; sh.u.ld.Wlo[r][nq + 1] = lo;
            split_half(wv.z, hi, lo); sh.u.ld.Whi[r][nq + 2] = hi; sh.u.ld.Wlo[r][nq + 2] = lo;
            split_half(wv.w, hi, lo); sh.u.ld.Whi[r][nq + 3] = hi; sh.u.ld.Wlo[r][nq + 3] = lo;
        }
        __syncthreads();

#pragma unroll
        for (int kk = 0; kk < 32; kk += 16) {
            wmma::fragment<wmma::matrix_a, 16, 16, 16, __half, wmma::row_major> ahi[2], alo[2];
            wmma::fragment<wmma::matrix_b, 16, 16, 16, __half, wmma::row_major> bhi[2], blo[2];
#pragma unroll
            for (int i = 0; i < 2; i++) {
                wmma::load_matrix_sync(ahi[i], &sh.u.ld.Ahi[wm * 32 + i * 16][kk], 40);
                wmma::load_matrix_sync(alo[i], &sh.u.ld.Alo[wm * 32 + i * 16][kk], 40);
            }
#pragma unroll
            for (int j = 0; j < 2; j++) {
                wmma::load_matrix_sync(bhi[j], &sh.u.ld.Whi[kk][wn * 32 + j * 16], 136);
                wmma::load_matrix_sync(blo[j], &sh.u.ld.Wlo[kk][wn * 32 + j * 16], 136);
            }
#pragma unroll
            for (int i = 0; i < 2; i++)
#pragma unroll
                for (int j = 0; j < 2; j++) {
                    wmma::mma_sync(c[i][j], ahi[i], bhi[j], c[i][j]);
                    wmma::mma_sync(c[i][j], alo[i], bhi[j], c[i][j]);
                    wmma::mma_sync(c[i][j], ahi[i], blo[j], c[i][j]);
                }
        }
        __syncthreads();
    }

    // write accumulators to smem, then epilogue
#pragma unroll
    for (int i = 0; i < 2; i++)
#pragma unroll
        for (int j = 0; j < 2; j++)
            wmma::store_matrix_sync(&sh.u.Csm[wm * 32 + i * 16][wn * 32 + j * 16],
                                    c[i][j], 132, wmma::mem_row_major);
    __syncthreads();

    int tx = tid & 31;           // col group of 4
    int ty = tid >> 5;           // 8 row groups of 8
    float bb[4];
#pragma unroll
    for (int j = 0; j < 4; j++) bb[j] = b[tx * 4 + j];
#pragma unroll
    for (int i = 0; i < 8; i++) {
        int r = ty * 8 + i;
        int row = row0 + r;
        if (row < NN) {
            float4 xv;
            xv.x = sh.u.Csm[r][tx * 4 + 0] + bb[0];
            xv.y = sh.u.Csm[r][tx * 4 + 1] + bb[1];
            xv.z = sh.u.Csm[r][tx * 4 + 2] + bb[2];
            xv.w = sh.u.Csm[r][tx * 4 + 3] + bb[3];
            float4 fv;
            fv.x = w0 * xv.x; fv.y = w0 * xv.y; fv.z = w0 * xv.z; fv.w = w0 * xv.w;
            __half2 h0 = __floats2half2_rn(xv.x, xv.y);
            __half2 h1 = __floats2half2_rn(xv.z, xv.w);
            uint2 u; u.x = *(unsigned*)&h0; u.y = *(unsigned*)&h1;
            *(uint2*)(X + (size_t)row * HID + tx * 4) = u;
            *(float4*)(F + (size_t)row * HID + tx * 4) = fv;
        }
    }
}

// ---------------- CSR gather SPMM (half in / half out, fp32 accumulate + feat) ----------------
__global__ __launch_bounds__(256) void spmm_kernel(int pp, int hop,
                                                   const float* __restrict__ wsp,
                                                   const float* __restrict__ wtp)
{
    int which = blockIdx.y;
    int w = (blockIdx.x * blockDim.x + threadIdx.x) >> 5;
    int lane = threadIdx.x & 31;
    if (w >= NN) return;

    const int* rp; const int2* ep;
    const __half* xin; __half* xout; float* feat; float wh;
    if (which == 0) {
        rp = g_rp;  ep = g_ep;  feat = g_fs; wh = wsp[hop];
        xin  = pp ? g_cs : g_xs;
        xout = pp ? g_xs : g_cs;
    } else {
        rp = g_rpT; ep = g_epT; feat = g_ft; wh = wtp[hop];
        xin  = pp ? g_ct : g_xt;
        xout = pp ? g_xt : g_ct;
    }

    int s = rp[w], e = rp[w + 1];
    float ax = 0.f, ay = 0.f, az = 0.f, aw = 0.f;
    for (int i = s; i < e; i++) {
        int2 pr = __ldg(&ep[i]);
        int   c = pr.x;
        float t = __int_as_float(pr.y);
        uint2 u = __ldg((const uint2*)(xin + (size_t)c * HID + lane * 4));
        __half2 h0 = *(__half2*)&u.x;
        __half2 h1 = *(__half2*)&u.y;
        float2 f0 = __half22float2(h0);
        float2 f1 = __half22float2(h1);
        ax += t * f0.x; ay += t * f0.y; az += t * f1.x; aw += t * f1.y;
    }
    size_t o = (size_t)w * HID + lane * 4;
    __half2 o0 = __floats2half2_rn(ax, ay);
    __half2 o1 = __floats2half2_rn(az, aw);
    uint2 uo; uo.x = *(unsigned*)&o0; uo.y = *(unsigned*)&o1;
    *(uint2*)(xout + o) = uo;
    float4 f = *(float4*)(feat + o);
    f.x += wh * ax; f.y += wh * ay; f.z += wh * az; f.w += wh * aw;
    *(float4*)(feat + o) = f;
}

// ---------------- output GEMM (tensor, split-3): out = [fs | ft] @ W_node + b_node ----------------
// BM=64, BN=64, BK=32; 128 threads = 4 warps (2x2), each warp 32x32
struct GOutShared {
    union {
        struct {
            __half Ahi[64][40];
            __half Alo[64][40];
            __half Whi[32][72];
            __half Wlo[32][72];
        } ld;
        float Csm[64][68];
    } u;
};

__global__ __launch_bounds__(128) void gemm_out_tc_kernel(
    const float* __restrict__ Wn, const float* __restrict__ bn, float* __restrict__ out)
{
    __shared__ GOutShared sh;
    int tid = threadIdx.x;
    int warp = tid >> 5;
    int wm = warp >> 1;          // 0..1
    int wn = warp & 1;           // 0..1
    int row0 = blockIdx.x * 64;

    wmma::fragment<wmma::accumulator, 16, 16, 16, float> c[2][2];
#pragma unroll
    for (int i = 0; i < 2; i++)
#pragma unroll
        for (int j = 0; j < 2; j++) wmma::fill_fragment(c[i][j], 0.f);

    for (int kt = 0; kt < 2 * HID; kt += 32) {
        const float* Abase = (kt < HID) ? g_fs : g_ft;
        int kloc = (kt < HID) ? kt : kt - HID;
        // A tile 64x32 = 512 float4, 4 per thread
#pragma unroll
        for (int t = 0; t < 4; t++) {
            int idx = tid + t * 128;
            int r = idx >> 3;
            int kq = (idx & 7) * 4;
            float4 av = make_float4(0.f, 0.f, 0.f, 0.f);
            int grow = row0 + r;
            if (grow < NN) av = *(const float4*)(Abase + (size_t)grow * HID + kloc + kq);
            __half hi, lo;
            split_half(av.x, hi, lo); sh.u.ld.Ahi[r][kq + 0] = hi; sh.u.ld.Alo[r][kq + 0] = lo;
            split_half(av.y, hi, lo); sh.u.ld.Ahi[r][kq + 1] = hi; sh.u.ld.Alo[r][kq + 1] = lo;
            split_half(av.z, hi, lo); sh.u.ld.Ahi[r][kq + 2] = hi; sh.u.ld.Alo[r][kq + 2] = lo;
            split_half(av.w, hi, lo); sh.u.ld.Ahi[r][kq + 3] = hi; sh.u.ld.Alo[r][kq + 3] = lo;
        }
        // W tile 32x64 = 512 float4, 4 per thread
#pragma unroll
        for (int t = 0; t < 4; t++) {
            int idx = tid + t * 128;
            int r = idx >> 4;
            int nq = (idx & 15) * 4;
            float4 wv = *(const float4*)(Wn + (size_t)(kt + r) * OUTD + nq);
            __half hi, lo;
            split_half(wv.x, hi, lo); sh.u.ld.Whi[r][nq + 0] = hi; sh.u.ld.Wlo[r][nq + 0] = lo;
            split_half(wv.y, hi, lo); sh.u.ld.Whi[r][nq + 1] = hi; sh.u.ld.Wlo[r][nq + 1] = lo;
            split_half(wv.z, hi, lo); sh.u.ld.Whi[r][nq + 2] = hi; sh.u.ld.Wlo[r][nq + 2] = lo;
            split_half(wv.w, hi, lo); sh.u.ld.Whi[r][nq + 3] = hi; sh.u.ld.Wlo[r][nq + 3] = lo;
        }
        __syncthreads();

#pragma unroll
        for (int kk = 0; kk < 32; kk += 16) {
            wmma::fragment<wmma::matrix_a, 16, 16, 16, __half, wmma::row_major> ahi[2], alo[2];
            wmma::fragment<wmma::matrix_b, 16, 16, 16, __half, wmma::row_major> bhi[2], blo[2];
#pragma unroll
            for (int i = 0; i < 2; i++) {
                wmma::load_matrix_sync(ahi[i], &sh.u.ld.Ahi[wm * 32 + i * 16][kk], 40);
                wmma::load_matrix_sync(alo[i], &sh.u.ld.Alo[wm * 32 + i * 16][kk], 40);
            }
#pragma unroll
            for (int j = 0; j < 2; j++) {
                wmma::load_matrix_sync(bhi[j], &sh.u.ld.Whi[kk][wn * 32 + j * 16], 72);
                wmma::load_matrix_sync(blo[j], &sh.u.ld.Wlo[kk][wn * 32 + j * 16], 72);
            }
#pragma unroll
            for (int i = 0; i < 2; i++)
#pragma unroll
                for (int j = 0; j < 2; j++) {
                    wmma::mma_sync(c[i][j], ahi[i], bhi[j], c[i][j]);
                    wmma::mma_sync(c[i][j], alo[i], bhi[j], c[i][j]);
                    wmma::mma_sync(c[i][j], ahi[i], blo[j], c[i][j]);
                }
        }
        __syncthreads();
    }

#pragma unroll
    for (int i = 0; i < 2; i++)
#pragma unroll
        for (int j = 0; j < 2; j++)
            wmma::store_matrix_sync(&sh.u.Csm[wm * 32 + i * 16][wn * 32 + j * 16],
                                    c[i][j], 68, wmma::mem_row_major);
    __syncthreads();

    int tx = tid & 15;           // 16 col groups of 4
    int ty = tid >> 4;           // 8 row groups of 8
    float bb[4];
#pragma unroll
    for (int j = 0; j < 4; j++) bb[j] = bn[tx * 4 + j];
#pragma unroll
    for (int i = 0; i < 8; i++) {
        int r = ty * 8 + i;
        int row = row0 + r;
        if (row < NN) {
            float4 ov;
            ov.x = sh.u.Csm[r][tx * 4 + 0] + bb[0];
            ov.y = sh.u.Csm[r][tx * 4 + 1] + bb[1];
            ov.z = sh.u.Csm[r][tx * 4 + 2] + bb[2];
            ov.w = sh.u.Csm[r][tx * 4 + 3] + bb[3];
            *(float4*)(out + (size_t)row * OUTD + tx * 4) = ov;
        }
    }
}

// ---------------- launch ----------------
extern "C" void kernel_launch(void* const* d_in, const int* in_sizes, int n_in,
                              void* d_out, int out_size)
{
    const float* fsrc  = (const float*)d_in[0];
    const float* ftgt  = (const float*)d_in[1];
    const int*   erow  = (const int*)d_in[2];
    const int*   ecol  = (const int*)d_in[3];
    const float* ew    = (const float*)d_in[4];
    const float* Wsrc  = (const float*)d_in[5];
    const float* bsrc  = (const float*)d_in[6];
    const float* Wtgt  = (const float*)d_in[7];
    const float* btgt  = (const float*)d_in[8];
    const float* ws    = (const float*)d_in[9];
    const float* wt    = (const float*)d_in[10];
    const float* Wnode = (const float*)d_in[11];
    const float* bnode = (const float*)d_in[12];
    float* out = (float*)d_out;
    int E = in_sizes[2];
    if (E > NE) E = NE;

    zero_deg_kernel<<<(NN + 255) / 256, 256>>>();

    dim3 gg((NN + 63) / 64, 2);
    gemm_in_tc_kernel<<<gg, 256>>>(fsrc, ftgt, Wsrc, bsrc, Wtgt, btgt, ws, wt);

    int eg = (E + 255) / 256;
    hist_kernel<<<eg, 256>>>(erow, ecol, E);
    dim3 sgr(NBLK, 2);
    scan_partial_kernel<<<sgr, SCB>>>();
    scan_part2_kernel<<<1, 64>>>();
    scan_final_kernel<<<sgr, SCB>>>(E);
    scatter_kernel<<<eg, 256>>>(erow, ecol, ew, E);

    dim3 sg((NN * 32 + 255) / 256, 2);  // one warp per row, y = path
    spmm_kernel<<<sg, 256>>>(0, 1, ws, wt);  // hop 1: x -> c
    spmm_kernel<<<sg, 256>>>(1, 2, ws, wt);  // hop 2: c -> x
    spmm_kernel<<<sg, 256>>>(0, 3, ws, wt);  // hop 3: x -> c

    gemm_out_tc_kernel<<<(NN + 63) / 64, 128>>>(Wnode, bnode, out);
}